// round 1
// baseline (speedup 1.0000x reference)
#include <cuda_runtime.h>
#include <cstdint>

// Problem constants (fixed by the dataset)
#define BATCH 4
#define C_IN 32
#define C_OUT 32
#define NNODE 163842
#define K7 7

// Scratch for the transposed x: [B, N, C_IN] floats = 4*163842*32 = 20,971,776 floats (~84 MB).
// __device__ global array (no cudaMalloc allowed).
__device__ float g_xt[(size_t)BATCH * NNODE * C_IN];

// ---------------------------------------------------------------------------
// Kernel 1: transpose x [B, C_IN, N] -> xt [B, N, C_IN]
// Classic 32x32 smem tile transpose, one 32-channel plane slice per block.
// ---------------------------------------------------------------------------
__global__ __launch_bounds__(256) void transpose_kernel(const float* __restrict__ x,
                                                        float* __restrict__ xt) {
    __shared__ float tile[32][33];  // +1 pad to kill bank conflicts
    const int b = blockIdx.y;
    const int n0 = blockIdx.x * 32;
    const int tx = threadIdx.x;  // 0..31
    const int ty = threadIdx.y;  // 0..7

    // Load: x[b][c][n0+tx], c = ty, ty+8, ... (coalesced along n)
    const int n_ld = n0 + tx;
#pragma unroll
    for (int c = ty; c < 32; c += 8) {
        float v = 0.0f;
        if (n_ld < NNODE) v = x[((size_t)b * C_IN + c) * NNODE + n_ld];
        tile[c][tx] = v;
    }
    __syncthreads();

    // Store: xt[b][n][c], c = tx (coalesced along c), n = n0 + r
#pragma unroll
    for (int r = ty; r < 32; r += 8) {
        const int n = n0 + r;
        if (n < NNODE) xt[((size_t)b * NNODE + n) * C_IN + tx] = tile[tx][r];
    }
}

// ---------------------------------------------------------------------------
// Kernel 2: per-node conv. Thread t handles node n = blockIdx.x*128 + t for
// batch b = blockIdx.y. Gathers 7 contiguous 128B neighbor rows from xt via
// LDG.128 into registers, W broadcast from smem via LDS.128 (conflict-free:
// all lanes read the same address), 32 fp32 accumulators, coalesced STG.
// ---------------------------------------------------------------------------
__global__ __launch_bounds__(128) void onering_conv_kernel(
    const float* __restrict__ xt,
    const float* __restrict__ W,      // [32][224], col index = k*32 + c
    const float* __restrict__ bias,   // [32]
    const int* __restrict__ neigh,    // [N][7]
    float* __restrict__ out) {        // [B][32][N]

    __shared__ float4 Ws[C_OUT * 56];  // 32 * 224/4 float4 = 28 KB
    __shared__ float bs[C_OUT];

    const int tid = threadIdx.x;

    // Cooperative load of W (1792 float4) and bias into smem.
    const float4* W4 = reinterpret_cast<const float4*>(W);
#pragma unroll
    for (int i = tid; i < C_OUT * 56; i += 128) Ws[i] = W4[i];
    if (tid < C_OUT) bs[tid] = bias[tid];
    __syncthreads();

    const int n = blockIdx.x * 128 + tid;
    const int b = blockIdx.y;
    if (n >= NNODE) return;

    float acc[C_OUT];
#pragma unroll
    for (int o = 0; o < C_OUT; o++) acc[o] = bs[o];

    // Keep the k-loop rolled: body ~1.1k instrs fits I$ comfortably.
#pragma unroll 1
    for (int k = 0; k < K7; k++) {
        const int m = neigh[n * K7 + k];
        const float4* p = reinterpret_cast<const float4*>(
            xt + ((size_t)b * NNODE + m) * C_IN);
        float4 v[8];
#pragma unroll
        for (int j = 0; j < 8; j++) v[j] = p[j];  // 128 contiguous bytes

#pragma unroll
        for (int o = 0; o < C_OUT; o++) {
            float s0 = 0.f, s1 = 0.f, s2 = 0.f, s3 = 0.f;
#pragma unroll
            for (int j = 0; j < 8; j++) {
                const float4 w = Ws[o * 56 + k * 8 + j];  // broadcast LDS.128
                s0 = fmaf(v[j].x, w.x, s0);
                s1 = fmaf(v[j].y, w.y, s1);
                s2 = fmaf(v[j].z, w.z, s2);
                s3 = fmaf(v[j].w, w.w, s3);
            }
            acc[o] += (s0 + s1) + (s2 + s3);
        }
    }

    // out[b][o][n]: coalesced across the warp for each o.
    float* outb = out + (size_t)b * C_OUT * NNODE + n;
#pragma unroll
    for (int o = 0; o < C_OUT; o++) outb[(size_t)o * NNODE] = acc[o];
}

// ---------------------------------------------------------------------------
// Launch. Inputs per metadata order: x, W, b, neigh_orders. Output fp32.
// Graph-capturable: two plain kernel launches on the default stream.
// ---------------------------------------------------------------------------
extern "C" void kernel_launch(void* const* d_in, const int* in_sizes, int n_in,
                              void* d_out, int out_size) {
    const float* x     = (const float*)d_in[0];
    const float* W     = (const float*)d_in[1];
    const float* bias  = (const float*)d_in[2];
    const int*   neigh = (const int*)d_in[3];
    float* out = (float*)d_out;

    float* xt = nullptr;
    cudaGetSymbolAddress((void**)&xt, g_xt);

    {
        dim3 block(32, 8);
        dim3 grid((NNODE + 31) / 32, BATCH);
        transpose_kernel<<<grid, block>>>(x, xt);
    }
    {
        dim3 block(128);
        dim3 grid((NNODE + 127) / 128, BATCH);
        onering_conv_kernel<<<grid, block>>>(xt, W, bias, neigh, out);
    }
}